// round 1
// baseline (speedup 1.0000x reference)
#include <cuda_runtime.h>
#include <cuda_bf16.h>

#define EPS_F 1e-6f

constexpr int C_DIM    = 128;   // channels
constexpr int T_TOK    = 16;    // tokens per block
constexpr int NTHREADS = 384;   // 3 warpgroups: q / k / v projections
constexpr int B_BATCH  = 4;
constexpr int N_TOK    = 1024;  // H*W

__device__ __forceinline__ float feature_map(float x) {
    // elu(x) + 1:  x>0 -> x+1 ;  x<=0 -> exp(x)
    return x > 0.0f ? x + 1.0f : __expf(x);
}

__global__ __launch_bounds__(NTHREADS, 2)
void rlsa_fused_kernel(const float* __restrict__ feat,
                       const float* __restrict__ wq, const float* __restrict__ bq,
                       const float* __restrict__ wk, const float* __restrict__ bk,
                       const float* __restrict__ wv, const float* __restrict__ bv,
                       float* __restrict__ out)
{
    __shared__ __align__(16) float xs[T_TOK][C_DIM];
    __shared__ __align__(16) float qs[T_TOK][C_DIM];
    __shared__ __align__(16) float ks[T_TOK][C_DIM];
    __shared__ __align__(16) float vs[T_TOK][C_DIM];
    __shared__ float s_sm[T_TOK];

    const int tid = threadIdx.x;
    const int g0  = blockIdx.x * T_TOK;     // first global token of this block
    const int b   = g0 >> 10;               // batch index (T divides 1024)
    const int n0  = g0 & (N_TOK - 1);

    // ---- 1. gather x tile: xs[t][i] = feature[b, i, n0+t] ----
    for (int idx = tid; idx < T_TOK * C_DIM; idx += NTHREADS) {
        int t = idx >> 7;
        int i = idx & (C_DIM - 1);
        xs[t][i] = feat[(((size_t)(b * C_DIM + i)) << 10) + (size_t)(n0 + t)];
    }
    __syncthreads();

    // ---- 2. projections: warpgroup per {q,k,v}, thread per output channel ----
    {
        const int proj = tid >> 7;          // 0=q, 1=k, 2=v
        const int o    = tid & (C_DIM - 1);
        const float* W  = (proj == 0) ? wq : (proj == 1) ? wk : wv;
        const float* Bp = (proj == 0) ? bq : (proj == 1) ? bk : bv;

        float acc[T_TOK];
        const float bias = __ldg(&Bp[o]);
        #pragma unroll
        for (int t = 0; t < T_TOK; t++) acc[t] = bias;

        const float4* Wr = reinterpret_cast<const float4*>(W + (size_t)o * C_DIM);
        #pragma unroll 2
        for (int i4 = 0; i4 < C_DIM / 4; i4++) {
            const float4 w = __ldg(&Wr[i4]);
            #pragma unroll
            for (int t = 0; t < T_TOK; t++) {
                const float4 xv = reinterpret_cast<const float4*>(xs[t])[i4];
                acc[t] = fmaf(w.x, xv.x, acc[t]);
                acc[t] = fmaf(w.y, xv.y, acc[t]);
                acc[t] = fmaf(w.z, xv.z, acc[t]);
                acc[t] = fmaf(w.w, xv.w, acc[t]);
            }
        }

        float* dst = (proj == 0) ? &qs[0][0] : (proj == 1) ? &ks[0][0] : &vs[0][0];
        if (proj < 2) {
            #pragma unroll
            for (int t = 0; t < T_TOK; t++) dst[t * C_DIM + o] = feature_map(acc[t]);
        } else {
            #pragma unroll
            for (int t = 0; t < T_TOK; t++) dst[t * C_DIM + o] = acc[t];
        }
    }
    __syncthreads();

    // ---- 3. per-token s = dot(Q, K), warp-parallel ----
    {
        const int warp = tid >> 5;
        const int lane = tid & 31;
        for (int t = warp; t < T_TOK; t += NTHREADS / 32) {
            float p = 0.0f;
            #pragma unroll
            for (int j = 0; j < C_DIM; j += 32)
                p = fmaf(qs[t][lane + j], ks[t][lane + j], p);
            #pragma unroll
            for (int off = 16; off; off >>= 1)
                p += __shfl_down_sync(0xffffffffu, p, off);
            if (lane == 0) s_sm[t] = p;
        }
    }
    __syncthreads();

    // ---- 4. write outputs: RLSA | Ri | Si (concatenated in return order) ----
    const size_t RLSA_SIZE = (size_t)B_BATCH * N_TOK * C_DIM;       // 524288
    float* rlsa = out;
    float* ri   = out + RLSA_SIZE;
    float* si   = out + RLSA_SIZE + RLSA_SIZE * (size_t)C_DIM;

    for (int t = 0; t < T_TOK; t++) {
        const int g = g0 + t;
        const float s  = s_sm[t];
        const float sc = s / (s + EPS_F);

        const float4* vrow = reinterpret_cast<const float4*>(vs[t]);
        const float4* krow = reinterpret_cast<const float4*>(ks[t]);
        float4* rip = reinterpret_cast<float4*>(ri + (size_t)g * (C_DIM * C_DIM));

        if (tid < 32) {
            const float4 v = vrow[tid];
            reinterpret_cast<float4*>(rlsa + (size_t)g * C_DIM)[tid] =
                make_float4(sc * v.x, sc * v.y, sc * v.z, sc * v.w);
            reinterpret_cast<float4*>(si + (size_t)g * C_DIM)[tid] = krow[tid];
        }

        // Ri tile: 128 rows x 32 float4; stride 384 = 12 whole rows per step
        // -> every warp instruction is a contiguous 512B STG burst.
        for (int idx = tid; idx < C_DIM * (C_DIM / 4); idx += NTHREADS) {
            const int c  = idx >> 5;
            const int mv = idx & 31;
            const float kc  = ks[t][c];      // warp-uniform broadcast
            const float4 v  = vrow[mv];      // conflict-free LDS.128
            rip[c * 32 + mv] = make_float4(kc * v.x, kc * v.y, kc * v.z, kc * v.w);
        }
    }
}

extern "C" void kernel_launch(void* const* d_in, const int* in_sizes, int n_in,
                              void* d_out, int out_size)
{
    const float* feat = (const float*)d_in[0];
    const float* wq   = (const float*)d_in[1];
    const float* bq   = (const float*)d_in[2];
    const float* wk   = (const float*)d_in[3];
    const float* bk   = (const float*)d_in[4];
    const float* wv   = (const float*)d_in[5];
    const float* bv   = (const float*)d_in[6];
    float* out = (float*)d_out;

    const int n_tokens = B_BATCH * N_TOK;           // 4096
    dim3 grid(n_tokens / T_TOK);                    // 256 blocks
    dim3 block(NTHREADS);
    rlsa_fused_kernel<<<grid, block>>>(feat, wq, bq, wk, bk, wv, bv, out);
}